// round 7
// baseline (speedup 1.0000x reference)
#include <cuda_runtime.h>
#include <math.h>
#include <stdint.h>

#define KDIM 256
#define DDIM 128
#define BB 4
#define TT 1024
#define NG 8
#define NITER 100
#define NSQ 20
#define LAMBDA 0.01f
#define REGV 0.01f
#define NTOT (BB*KDIM*TT)

// ======================= device scratch =======================
__device__ float g_DtD[KDIM*KDIM];
__device__ float g_At[KDIM*KDIM];          // A^T, A = I - DtD/L
__device__ float g_GG[DDIM*DDIM];          // D*D^T (128x128), same nonzero spectrum
__device__ float g_M[2][DDIM*DDIM];        // squaring ping-pong
__device__ float g_scale[NSQ+1];
__device__ float g_Linv, g_lambd;
__device__ float g_DtY[NTOT];
__device__ float g_xb[2][NTOT];            // ping-pong x
__device__ float g_l1[2][NTOT];            // ping-pong l1
__device__ float g_gsum[NITER][NG];

__device__ __forceinline__ void atomicMaxPosF(float* a, float v){
    atomicMax((int*)a, __float_as_int(v));
}

// ---------------- init ----------------
__global__ void k_init(const float* __restrict__ x0){
    int i = blockIdx.x*blockDim.x + threadIdx.x;
    if (i < NTOT) g_xb[0][i] = x0[i];
    if (i < NITER*NG) ((float*)g_gsum)[i]=0.f;
    if (i <= NSQ) g_scale[i]=0.f;
}

// ---------------- DtD = D^T D (256x256) ----------------
__global__ void k_dtd(const float* __restrict__ Dict){
    int i=blockIdx.x, j=threadIdx.x;
    float a0=0.f,a1=0.f,a2=0.f,a3=0.f;
    #pragma unroll 8
    for(int d=0; d<DDIM; d+=4){
        a0 += Dict[(d  )*KDIM+i]*Dict[(d  )*KDIM+j];
        a1 += Dict[(d+1)*KDIM+i]*Dict[(d+1)*KDIM+j];
        a2 += Dict[(d+2)*KDIM+i]*Dict[(d+2)*KDIM+j];
        a3 += Dict[(d+3)*KDIM+i]*Dict[(d+3)*KDIM+j];
    }
    g_DtD[i*KDIM+j]=(a0+a1)+(a2+a3);
}

// ---------------- GG = D D^T (128x128) ----------------
__global__ void k_gg(const float* __restrict__ Dict){
    __shared__ float sh[KDIM];
    int i=blockIdx.x, j=threadIdx.x;
    sh[j]        = Dict[i*KDIM + j];
    sh[j+128]    = Dict[i*KDIM + j + 128];
    __syncthreads();
    float a0=0.f,a1=0.f,a2=0.f,a3=0.f;
    const float* rj = Dict + j*KDIM;
    #pragma unroll 8
    for(int k=0;k<KDIM;k+=4){
        a0 += sh[k  ]*rj[k  ];
        a1 += sh[k+1]*rj[k+1];
        a2 += sh[k+2]*rj[k+2];
        a3 += sh[k+3]*rj[k+3];
    }
    float acc=(a0+a1)+(a2+a3);
    g_GG[i*DDIM+j]=acc;
    float m=fabsf(acc);
    #pragma unroll
    for(int o=16;o>0;o>>=1) m=fmaxf(m,__shfl_xor_sync(0xffffffffu,m,o));
    __shared__ float sm[4];
    if((j&31)==0) sm[j>>5]=m;
    __syncthreads();
    if(j==0){
        float mm=fmaxf(fmaxf(sm[0],sm[1]),fmaxf(sm[2],sm[3]));
        atomicMaxPosF(&g_scale[0], mm);
    }
}

// ---------------- 128x128 matrix squaring ----------------
__global__ void k_square(int step){
    const float* __restrict__ in = (step==0)? g_GG : g_M[(step-1)&1];
    float* __restrict__ out = g_M[step&1];
    __shared__ float sh[DDIM];
    int i=blockIdx.x, j=threadIdx.x;
    sh[j]=in[i*DDIM+j];
    __syncthreads();
    float inv = 1.0f/g_scale[step];
    float a0=0.f,a1=0.f,a2=0.f,a3=0.f;
    #pragma unroll 8
    for(int p=0;p<DDIM;p+=4){
        a0 += sh[p  ]*in[(p  )*DDIM+j];
        a1 += sh[p+1]*in[(p+1)*DDIM+j];
        a2 += sh[p+2]*in[(p+2)*DDIM+j];
        a3 += sh[p+3]*in[(p+3)*DDIM+j];
    }
    float acc=((a0+a1)+(a2+a3))*inv*inv;
    out[i*DDIM+j]=acc;
    float m=fabsf(acc);
    #pragma unroll
    for(int o=16;o>0;o>>=1) m=fmaxf(m,__shfl_xor_sync(0xffffffffu,m,o));
    __shared__ float sm[4];
    if((j&31)==0) sm[j>>5]=m;
    __syncthreads();
    if(j==0){
        float mm=fmaxf(fmaxf(sm[0],sm[1]),fmaxf(sm[2],sm[3]));
        atomicMaxPosF(&g_scale[step+1], mm);
    }
}

// ---------------- Rayleigh quotient on GG ----------------
__global__ void k_rayleigh(int bufidx){
    const float* __restrict__ Mf = g_M[bufidx];
    __shared__ float v[DDIM];
    __shared__ float red[DDIM];
    __shared__ int rid[DDIM];
    int j=threadIdx.x;
    red[j]=Mf[j*DDIM+j]; rid[j]=j;
    __syncthreads();
    for(int s=DDIM/2;s>0;s>>=1){
        if(j<s && red[j+s]>red[j]){ red[j]=red[j+s]; rid[j]=rid[j+s]; }
        __syncthreads();
    }
    int jstar=rid[0];
    __syncthreads();
    v[j]=Mf[j*DDIM+jstar];
    __syncthreads();
    float u=0.f;
    #pragma unroll 8
    for(int p=0;p<DDIM;p++) u += g_GG[j*DDIM+p]*v[p];
    float num=u*v[j], den=v[j]*v[j];
    red[j]=num; __syncthreads();
    for(int s=DDIM/2;s>0;s>>=1){ if(j<s) red[j]+=red[j+s]; __syncthreads(); }
    float NUM=red[0]; __syncthreads();
    red[j]=den; __syncthreads();
    for(int s=DDIM/2;s>0;s>>=1){ if(j<s) red[j]+=red[j+s]; __syncthreads(); }
    if(j==0){
        float L = NUM/red[0];
        g_Linv = 1.0f/L;
        g_lambd = LAMBDA/L;
    }
}

// ---------------- A^T build (transposed so GEMM tile loads coalesce) ----------------
__global__ void k_buildAt(){
    int i=blockIdx.x, j=threadIdx.x;
    float a = ((i==j)?1.f:0.f) - g_DtD[i*KDIM+j]*g_Linv;
    g_At[j*KDIM+i]=a;
}

// ---------------- DtY (fp32 SIMT, one-time) ----------------
__global__ void k_dty(const float* __restrict__ Dict, const float* __restrict__ inp){
    __shared__ float As[16][64];
    __shared__ float Bs[16][64];
    int tbase=blockIdx.x<<6, kbase=blockIdx.y<<6, b=blockIdx.z;
    int tid=threadIdx.x, tx=tid&15, ty=tid>>4;
    float acc[4][4];
    #pragma unroll
    for(int i=0;i<4;i++){
        #pragma unroll
        for(int q=0;q<4;q++) acc[i][q]=0.f;
    }
    for(int d0=0; d0<DDIM; d0+=16){
        #pragma unroll
        for(int r=0;r<4;r++){
            int e=tid + (r<<8);
            int dd=e>>6, cc=e&63;
            As[dd][cc]=Dict[(d0+dd)*KDIM + kbase+cc];
            Bs[dd][cc]=inp[(b*DDIM + d0+dd)*TT + tbase+cc];
        }
        __syncthreads();
        #pragma unroll
        for(int p=0;p<16;p++){
            float4 a=*(const float4*)&As[p][ty<<2];
            float4 bv=*(const float4*)&Bs[p][tx<<2];
            acc[0][0]+=a.x*bv.x; acc[0][1]+=a.x*bv.y; acc[0][2]+=a.x*bv.z; acc[0][3]+=a.x*bv.w;
            acc[1][0]+=a.y*bv.x; acc[1][1]+=a.y*bv.y; acc[1][2]+=a.y*bv.z; acc[1][3]+=a.y*bv.w;
            acc[2][0]+=a.z*bv.x; acc[2][1]+=a.z*bv.y; acc[2][2]+=a.z*bv.z; acc[2][3]+=a.z*bv.w;
            acc[3][0]+=a.w*bv.x; acc[3][1]+=a.w*bv.y; acc[3][2]+=a.w*bv.z; acc[3][3]+=a.w*bv.w;
        }
        __syncthreads();
    }
    #pragma unroll
    for(int i=0;i<4;i++){
        int kg=kbase+(ty<<2)+i;
        float4 o=make_float4(acc[i][0],acc[i][1],acc[i][2],acc[i][3]);
        *(float4*)&g_DtY[(b*KDIM+kg)*TT + tbase + (tx<<2)] = o;
    }
}

// ====== fused iteration: momentum+staging -> SIMT fp32 GEMM -> prox (R1 arithmetic) ======
// Grid (TT/64=16, KDIM/64=4, BB=4), 256 threads.
__global__ void __launch_bounds__(256,2) k_iter(int it, float coef, int first){
    __shared__ float As[16][64];
    __shared__ float Bs[16][64];
    __shared__ float sred[8];
    int tbase=blockIdx.x<<6, kbase=blockIdx.y<<6, b=blockIdx.z;
    int tid=threadIdx.x, tx=tid&15, ty=tid>>4;

    const float* __restrict__ l1r = g_l1[(it+1)&1];
    float* __restrict__ l1w       = g_l1[it&1];
    const float* __restrict__ xr  = first ? g_xb[0] : g_xb[(it+1)&1];
    float* __restrict__ xw        = g_xb[it&1];
    const float* __restrict__ gs  = g_gsum[it>0 ? it-1 : 0];
    int writer = (blockIdx.y==0);   // dedupe x writes: only kbase==0 CTAs write xw

    float acc[4][4];
    #pragma unroll
    for(int i=0;i<4;i++){
        #pragma unroll
        for(int q=0;q<4;q++) acc[i][q]=0.f;
    }

    for(int j0=0;j0<KDIM;j0+=16){
        #pragma unroll
        for(int r=0;r<4;r++){
            int e=tid+(r<<8);
            int jj=e>>6, cc=e&63;
            int jg=j0+jj;
            As[jj][cc]=g_At[jg*KDIM + kbase+cc];
            size_t idx = ((size_t)(b*KDIM + jg))*TT + tbase + cc;
            float v;
            if (first){
                v = xr[idx];
            } else {
                float s = gs[jg>>5];
                float scale = (s>0.f)? fmaxf(0.f, 1.f - REGV/sqrtf(s)) : 0.f;
                float nx = l1r[idx]*scale;
                float xo = xr[idx];
                v = nx + (nx - xo)*coef;
                if (writer) xw[idx] = nx;
            }
            Bs[jj][cc]=v;
        }
        __syncthreads();
        #pragma unroll
        for(int p=0;p<16;p++){
            float4 a=*(const float4*)&As[p][ty<<2];
            float4 bv=*(const float4*)&Bs[p][tx<<2];
            acc[0][0]+=a.x*bv.x; acc[0][1]+=a.x*bv.y; acc[0][2]+=a.x*bv.z; acc[0][3]+=a.x*bv.w;
            acc[1][0]+=a.y*bv.x; acc[1][1]+=a.y*bv.y; acc[1][2]+=a.y*bv.z; acc[1][3]+=a.y*bv.w;
            acc[2][0]+=a.z*bv.x; acc[2][1]+=a.z*bv.y; acc[2][2]+=a.z*bv.z; acc[2][3]+=a.z*bv.w;
            acc[3][0]+=a.w*bv.x; acc[3][1]+=a.w*bv.y; acc[3][2]+=a.w*bv.z; acc[3][3]+=a.w*bv.w;
        }
        __syncthreads();
    }

    // ---- epilogue: + DtY*Linv, soft-threshold, write l1, group ssq ----
    float Linv=g_Linv, lam=g_lambd;
    float ssq=0.f;
    #pragma unroll
    for(int i=0;i<4;i++){
        int kg=kbase+(ty<<2)+i;
        size_t base=((size_t)(b*KDIM+kg))*TT + tbase + (tx<<2);
        float4 dty=*(const float4*)&g_DtY[base];
        float s0=acc[i][0]+dty.x*Linv;
        float s1=acc[i][1]+dty.y*Linv;
        float s2=acc[i][2]+dty.z*Linv;
        float s3=acc[i][3]+dty.w*Linv;
        float v0=fmaxf(s0-lam,0.f)+fminf(s0+lam,0.f);
        float v1=fmaxf(s1-lam,0.f)+fminf(s1+lam,0.f);
        float v2=fmaxf(s2-lam,0.f)+fminf(s2+lam,0.f);
        float v3=fmaxf(s3-lam,0.f)+fminf(s3+lam,0.f);
        *(float4*)&l1w[base]=make_float4(v0,v1,v2,v3);
        ssq += v0*v0+v1*v1+v2*v2+v3*v3;
    }
    // warps 0..3 cover k in [kbase,kbase+32); warps 4..7 the next group
    #pragma unroll
    for(int o=16;o>0;o>>=1) ssq += __shfl_xor_sync(0xffffffffu, ssq, o);
    if((tid&31)==0) sred[tid>>5]=ssq;
    __syncthreads();
    if(tid==0)   atomicAdd(&g_gsum[it][(kbase>>5)  ], sred[0]+sred[1]+sred[2]+sred[3]);
    if(tid==128) atomicAdd(&g_gsum[it][(kbase>>5)+1], sred[4]+sred[5]+sred[6]+sred[7]);
}

// ---------------- final: x_100 = l1_99 * group_scale(gsum_99) ----------------
__global__ void k_final(float* __restrict__ dout){
    int i = blockIdx.x*blockDim.x + threadIdx.x;
    int idx = i<<2;
    int k = (idx>>10) & (KDIM-1);
    float s = g_gsum[NITER-1][k>>5];
    float scale = (s>0.f)? fmaxf(0.f, 1.f - REGV/sqrtf(s)) : 0.f;
    float4 l1 = *(const float4*)&g_l1[(NITER-1)&1][idx];
    *(float4*)&dout[idx] = make_float4(l1.x*scale, l1.y*scale, l1.z*scale, l1.w*scale);
}

// ======================= host launcher =======================
extern "C" void kernel_launch(void* const* d_in, const int* in_sizes, int n_in,
                              void* d_out, int out_size) {
    const float *Dict=nullptr, *inp=nullptr, *x0=nullptr;
    for(int i=0;i<n_in;i++){
        if      (in_sizes[i]==KDIM*DDIM)  Dict=(const float*)d_in[i];
        else if (in_sizes[i]==BB*DDIM*TT) inp =(const float*)d_in[i];
        else if (in_sizes[i]==NTOT)       x0  =(const float*)d_in[i];
    }
    float* out=(float*)d_out;

    k_init<<<(NTOT+255)/256,256>>>(x0);
    k_dtd<<<KDIM,KDIM>>>(Dict);
    k_gg<<<DDIM,DDIM>>>(Dict);
    for(int s=0;s<NSQ;s++) k_square<<<DDIM,DDIM>>>(s);
    k_rayleigh<<<1,DDIM>>>((NSQ-1)&1);
    k_buildAt<<<KDIM,KDIM>>>();
    k_dty<<<dim3(TT/64, KDIM/64, BB),256>>>(Dict, inp);

    float mom=1.f;
    for(int it=0; it<NITER; it++){
        float coef=0.f;
        int first = (it==0)?1:0;
        if(!first){
            float nm = 0.5f + 0.5f*sqrtf(1.f + 4.f*mom*mom);
            coef = (mom-1.f)/nm;
            mom = nm;
        }
        k_iter<<<dim3(TT/64, KDIM/64, BB), 256>>>(it, coef, first);
    }
    k_final<<<NTOT/4/256,256>>>(out);
}

// round 8
// speedup vs baseline: 1.8580x; 1.8580x over previous
#include <cuda_runtime.h>
#include <math.h>
#include <stdint.h>

#define KDIM 256
#define DDIM 128
#define BB 4
#define TT 1024
#define NG 8
#define NITER 100
#define NSQ 12
#define LAMBDA 0.01f
#define REGV 0.01f
#define NTOT (BB*KDIM*TT)

// ======================= device scratch =======================
__device__ float g_DtD[KDIM*KDIM];
__device__ float g_At[KDIM*KDIM];          // A^T, A = I - DtD/L
__device__ float g_GG[DDIM*DDIM];          // D*D^T (128x128), same nonzero spectrum
__device__ float g_M[2][DDIM*DDIM];        // squaring ping-pong
__device__ float g_scale[NSQ+1];
__device__ float g_Linv, g_lambd;
__device__ float g_DtY[NTOT];
__device__ float g_xb[2][NTOT];            // ping-pong x
__device__ float g_l1[2][NTOT];            // ping-pong l1
__device__ float g_gsum[NITER][NG];

__device__ __forceinline__ void atomicMaxPosF(float* a, float v){
    atomicMax((int*)a, __float_as_int(v));
}

// ---------------- init ----------------
__global__ void k_init(const float* __restrict__ x0){
    int i = blockIdx.x*blockDim.x + threadIdx.x;
    if (i < NTOT) g_xb[0][i] = x0[i];
    if (i < NITER*NG) ((float*)g_gsum)[i]=0.f;
    if (i <= NSQ) g_scale[i]=0.f;
}

// ---------------- DtD = D^T D (256x256) ----------------
__global__ void k_dtd(const float* __restrict__ Dict){
    int i=blockIdx.x, j=threadIdx.x;
    float a0=0.f,a1=0.f,a2=0.f,a3=0.f;
    #pragma unroll 8
    for(int d=0; d<DDIM; d+=4){
        a0 += Dict[(d  )*KDIM+i]*Dict[(d  )*KDIM+j];
        a1 += Dict[(d+1)*KDIM+i]*Dict[(d+1)*KDIM+j];
        a2 += Dict[(d+2)*KDIM+i]*Dict[(d+2)*KDIM+j];
        a3 += Dict[(d+3)*KDIM+i]*Dict[(d+3)*KDIM+j];
    }
    g_DtD[i*KDIM+j]=(a0+a1)+(a2+a3);
}

// ---------------- GG = D D^T (128x128) ----------------
__global__ void k_gg(const float* __restrict__ Dict){
    __shared__ float sh[KDIM];
    int i=blockIdx.x, j=threadIdx.x;
    sh[j]        = Dict[i*KDIM + j];
    sh[j+128]    = Dict[i*KDIM + j + 128];
    __syncthreads();
    float a0=0.f,a1=0.f,a2=0.f,a3=0.f;
    const float* rj = Dict + j*KDIM;
    #pragma unroll 8
    for(int k=0;k<KDIM;k+=4){
        a0 += sh[k  ]*rj[k  ];
        a1 += sh[k+1]*rj[k+1];
        a2 += sh[k+2]*rj[k+2];
        a3 += sh[k+3]*rj[k+3];
    }
    float acc=(a0+a1)+(a2+a3);
    g_GG[i*DDIM+j]=acc;
    float m=fabsf(acc);
    #pragma unroll
    for(int o=16;o>0;o>>=1) m=fmaxf(m,__shfl_xor_sync(0xffffffffu,m,o));
    __shared__ float sm[4];
    if((j&31)==0) sm[j>>5]=m;
    __syncthreads();
    if(j==0){
        float mm=fmaxf(fmaxf(sm[0],sm[1]),fmaxf(sm[2],sm[3]));
        atomicMaxPosF(&g_scale[0], mm);
    }
}

// ---------------- 128x128 matrix squaring ----------------
__global__ void k_square(int step){
    const float* __restrict__ in = (step==0)? g_GG : g_M[(step-1)&1];
    float* __restrict__ out = g_M[step&1];
    __shared__ float sh[DDIM];
    int i=blockIdx.x, j=threadIdx.x;
    sh[j]=in[i*DDIM+j];
    __syncthreads();
    float inv = 1.0f/g_scale[step];
    float a0=0.f,a1=0.f,a2=0.f,a3=0.f;
    #pragma unroll 8
    for(int p=0;p<DDIM;p+=4){
        a0 += sh[p  ]*in[(p  )*DDIM+j];
        a1 += sh[p+1]*in[(p+1)*DDIM+j];
        a2 += sh[p+2]*in[(p+2)*DDIM+j];
        a3 += sh[p+3]*in[(p+3)*DDIM+j];
    }
    float acc=((a0+a1)+(a2+a3))*inv*inv;
    out[i*DDIM+j]=acc;
    float m=fabsf(acc);
    #pragma unroll
    for(int o=16;o>0;o>>=1) m=fmaxf(m,__shfl_xor_sync(0xffffffffu,m,o));
    __shared__ float sm[4];
    if((j&31)==0) sm[j>>5]=m;
    __syncthreads();
    if(j==0){
        float mm=fmaxf(fmaxf(sm[0],sm[1]),fmaxf(sm[2],sm[3]));
        atomicMaxPosF(&g_scale[step+1], mm);
    }
}

// ---------------- Rayleigh quotient on GG ----------------
__global__ void k_rayleigh(int bufidx){
    const float* __restrict__ Mf = g_M[bufidx];
    __shared__ float v[DDIM];
    __shared__ float red[DDIM];
    __shared__ int rid[DDIM];
    int j=threadIdx.x;
    red[j]=Mf[j*DDIM+j]; rid[j]=j;
    __syncthreads();
    for(int s=DDIM/2;s>0;s>>=1){
        if(j<s && red[j+s]>red[j]){ red[j]=red[j+s]; rid[j]=rid[j+s]; }
        __syncthreads();
    }
    int jstar=rid[0];
    __syncthreads();
    v[j]=Mf[j*DDIM+jstar];
    __syncthreads();
    float u=0.f;
    #pragma unroll 8
    for(int p=0;p<DDIM;p++) u += g_GG[j*DDIM+p]*v[p];
    float num=u*v[j], den=v[j]*v[j];
    red[j]=num; __syncthreads();
    for(int s=DDIM/2;s>0;s>>=1){ if(j<s) red[j]+=red[j+s]; __syncthreads(); }
    float NUM=red[0]; __syncthreads();
    red[j]=den; __syncthreads();
    for(int s=DDIM/2;s>0;s>>=1){ if(j<s) red[j]+=red[j+s]; __syncthreads(); }
    if(j==0){
        float L = NUM/red[0];
        g_Linv = 1.0f/L;
        g_lambd = LAMBDA/L;
    }
}

// ---------------- A^T build ----------------
__global__ void k_buildAt(){
    int i=blockIdx.x, j=threadIdx.x;
    float a = ((i==j)?1.f:0.f) - g_DtD[i*KDIM+j]*g_Linv;
    g_At[j*KDIM+i]=a;
}

// ---------------- DtY (fp32 SIMT, one-time) ----------------
__global__ void k_dty(const float* __restrict__ Dict, const float* __restrict__ inp){
    __shared__ float As[16][64];
    __shared__ float Bs[16][64];
    int tbase=blockIdx.x<<6, kbase=blockIdx.y<<6, b=blockIdx.z;
    int tid=threadIdx.x, tx=tid&15, ty=tid>>4;
    float acc[4][4];
    #pragma unroll
    for(int i=0;i<4;i++){
        #pragma unroll
        for(int q=0;q<4;q++) acc[i][q]=0.f;
    }
    for(int d0=0; d0<DDIM; d0+=16){
        #pragma unroll
        for(int r=0;r<4;r++){
            int e=tid + (r<<8);
            int dd=e>>6, cc=e&63;
            As[dd][cc]=Dict[(d0+dd)*KDIM + kbase+cc];
            Bs[dd][cc]=inp[(b*DDIM + d0+dd)*TT + tbase+cc];
        }
        __syncthreads();
        #pragma unroll
        for(int p=0;p<16;p++){
            float4 a=*(const float4*)&As[p][ty<<2];
            float4 bv=*(const float4*)&Bs[p][tx<<2];
            acc[0][0]+=a.x*bv.x; acc[0][1]+=a.x*bv.y; acc[0][2]+=a.x*bv.z; acc[0][3]+=a.x*bv.w;
            acc[1][0]+=a.y*bv.x; acc[1][1]+=a.y*bv.y; acc[1][2]+=a.y*bv.z; acc[1][3]+=a.y*bv.w;
            acc[2][0]+=a.z*bv.x; acc[2][1]+=a.z*bv.y; acc[2][2]+=a.z*bv.z; acc[2][3]+=a.z*bv.w;
            acc[3][0]+=a.w*bv.x; acc[3][1]+=a.w*bv.y; acc[3][2]+=a.w*bv.z; acc[3][3]+=a.w*bv.w;
        }
        __syncthreads();
    }
    #pragma unroll
    for(int i=0;i<4;i++){
        int kg=kbase+(ty<<2)+i;
        float4 o=make_float4(acc[i][0],acc[i][1],acc[i][2],acc[i][3]);
        *(float4*)&g_DtY[(b*KDIM+kg)*TT + tbase + (tx<<2)] = o;
    }
}

// ====== fused iteration v2: 128x64 tile, 8x4 register blocking, hoisted scales ======
// Grid (TT/64=16, KDIM/128=2, BB=4) = 128 CTAs, 256 threads.
__global__ void __launch_bounds__(256,2) k_iter(int it, float coef, int first){
    __shared__ float As[16][128];   // [j-chunk][k-out]
    __shared__ float Bs[16][64];    // [j-chunk][t]
    __shared__ float sc[NG];
    int tid=threadIdx.x, tx=tid&15, ty=tid>>4, w=tid>>5, lane=tid&31;
    int tbase=blockIdx.x<<6, kbase=blockIdx.y<<7, b=blockIdx.z;

    const float* __restrict__ l1r = g_l1[(it+1)&1];
    float* __restrict__ l1w       = g_l1[it&1];
    const float* __restrict__ xr  = first ? g_xb[0] : g_xb[(it+1)&1];
    float* __restrict__ xw        = g_xb[it&1];
    int writer = (blockIdx.y==0);

    if (tid < NG){
        float s = g_gsum[it>0 ? it-1 : 0][tid];
        sc[tid] = (s>0.f)? fmaxf(0.f, 1.f - REGV/sqrtf(s)) : 0.f;
    }
    __syncthreads();

    float acc[8][4];
    #pragma unroll
    for(int i=0;i<8;i++){
        #pragma unroll
        for(int q=0;q<4;q++) acc[i][q]=0.f;
    }

    for(int c=0;c<16;c++){
        int jg = c*16 + ty;
        // ---- stage A: 16 x 128 (2 float4 per thread) ----
        {
            const float4* src=(const float4*)&g_At[jg*KDIM + kbase + tx*8];
            *(float4*)&As[ty][tx*8]   = src[0];
            *(float4*)&As[ty][tx*8+4] = src[1];
        }
        // ---- stage B: 16 x 64 with fused momentum (1 float4 per thread) ----
        {
            size_t idx = ((size_t)(b*KDIM + jg))*TT + tbase + tx*4;
            float4 v;
            if (first){
                v = *(const float4*)&xr[idx];
            } else {
                float scale = sc[jg>>5];
                float4 l1v = *(const float4*)&l1r[idx];
                float4 xo  = *(const float4*)&xr[idx];
                float nx0=l1v.x*scale, nx1=l1v.y*scale, nx2=l1v.z*scale, nx3=l1v.w*scale;
                v.x = nx0 + (nx0-xo.x)*coef;
                v.y = nx1 + (nx1-xo.y)*coef;
                v.z = nx2 + (nx2-xo.z)*coef;
                v.w = nx3 + (nx3-xo.w)*coef;
                if (writer) *(float4*)&xw[idx] = make_float4(nx0,nx1,nx2,nx3);
            }
            *(float4*)&Bs[ty][tx*4] = v;
        }
        __syncthreads();
        // ---- compute: 16 p-steps x (8x4) FMA ----
        #pragma unroll
        for(int p=0;p<16;p++){
            float4 a0=*(const float4*)&As[p][ty*8];
            float4 a1=*(const float4*)&As[p][ty*8+4];
            float4 bv=*(const float4*)&Bs[p][tx*4];
            acc[0][0]+=a0.x*bv.x; acc[0][1]+=a0.x*bv.y; acc[0][2]+=a0.x*bv.z; acc[0][3]+=a0.x*bv.w;
            acc[1][0]+=a0.y*bv.x; acc[1][1]+=a0.y*bv.y; acc[1][2]+=a0.y*bv.z; acc[1][3]+=a0.y*bv.w;
            acc[2][0]+=a0.z*bv.x; acc[2][1]+=a0.z*bv.y; acc[2][2]+=a0.z*bv.z; acc[2][3]+=a0.z*bv.w;
            acc[3][0]+=a0.w*bv.x; acc[3][1]+=a0.w*bv.y; acc[3][2]+=a0.w*bv.z; acc[3][3]+=a0.w*bv.w;
            acc[4][0]+=a1.x*bv.x; acc[4][1]+=a1.x*bv.y; acc[4][2]+=a1.x*bv.z; acc[4][3]+=a1.x*bv.w;
            acc[5][0]+=a1.y*bv.x; acc[5][1]+=a1.y*bv.y; acc[5][2]+=a1.y*bv.z; acc[5][3]+=a1.y*bv.w;
            acc[6][0]+=a1.z*bv.x; acc[6][1]+=a1.z*bv.y; acc[6][2]+=a1.z*bv.z; acc[6][3]+=a1.z*bv.w;
            acc[7][0]+=a1.w*bv.x; acc[7][1]+=a1.w*bv.y; acc[7][2]+=a1.w*bv.z; acc[7][3]+=a1.w*bv.w;
        }
        __syncthreads();
    }

    // ---- epilogue: + DtY*Linv, soft-threshold, write l1, group ssq ----
    float Linv=g_Linv, lam=g_lambd;
    float ssq=0.f;
    #pragma unroll
    for(int i=0;i<8;i++){
        int row = kbase + ty*8 + i;
        size_t base=((size_t)(b*KDIM+row))*TT + tbase + tx*4;
        float4 dty=*(const float4*)&g_DtY[base];
        float s0=acc[i][0]+dty.x*Linv;
        float s1=acc[i][1]+dty.y*Linv;
        float s2=acc[i][2]+dty.z*Linv;
        float s3=acc[i][3]+dty.w*Linv;
        float v0=fmaxf(s0-lam,0.f)+fminf(s0+lam,0.f);
        float v1=fmaxf(s1-lam,0.f)+fminf(s1+lam,0.f);
        float v2=fmaxf(s2-lam,0.f)+fminf(s2+lam,0.f);
        float v3=fmaxf(s3-lam,0.f)+fminf(s3+lam,0.f);
        *(float4*)&l1w[base]=make_float4(v0,v1,v2,v3);
        ssq += v0*v0+v1*v1+v2*v2+v3*v3;
    }
    // whole warp lies in one 32-row group: rows kbase+16w .. kbase+16w+15
    #pragma unroll
    for(int o=16;o>0;o>>=1) ssq += __shfl_xor_sync(0xffffffffu, ssq, o);
    if (lane==0) atomicAdd(&g_gsum[it][blockIdx.y*4 + (w>>1)], ssq);
}

// ---------------- final: x_100 = l1_99 * group_scale(gsum_99) ----------------
__global__ void k_final(float* __restrict__ dout){
    int i = blockIdx.x*blockDim.x + threadIdx.x;
    int idx = i<<2;
    int k = (idx>>10) & (KDIM-1);
    float s = g_gsum[NITER-1][k>>5];
    float scale = (s>0.f)? fmaxf(0.f, 1.f - REGV/sqrtf(s)) : 0.f;
    float4 l1 = *(const float4*)&g_l1[(NITER-1)&1][idx];
    *(float4*)&dout[idx] = make_float4(l1.x*scale, l1.y*scale, l1.z*scale, l1.w*scale);
}

// ======================= host launcher =======================
extern "C" void kernel_launch(void* const* d_in, const int* in_sizes, int n_in,
                              void* d_out, int out_size) {
    const float *Dict=nullptr, *inp=nullptr, *x0=nullptr;
    for(int i=0;i<n_in;i++){
        if      (in_sizes[i]==KDIM*DDIM)  Dict=(const float*)d_in[i];
        else if (in_sizes[i]==BB*DDIM*TT) inp =(const float*)d_in[i];
        else if (in_sizes[i]==NTOT)       x0  =(const float*)d_in[i];
    }
    float* out=(float*)d_out;

    k_init<<<(NTOT+255)/256,256>>>(x0);
    k_dtd<<<KDIM,KDIM>>>(Dict);
    k_gg<<<DDIM,DDIM>>>(Dict);
    for(int s=0;s<NSQ;s++) k_square<<<DDIM,DDIM>>>(s);
    k_rayleigh<<<1,DDIM>>>((NSQ-1)&1);
    k_buildAt<<<KDIM,KDIM>>>();
    k_dty<<<dim3(TT/64, KDIM/64, BB),256>>>(Dict, inp);

    float mom=1.f;
    for(int it=0; it<NITER; it++){
        float coef=0.f;
        int first = (it==0)?1:0;
        if(!first){
            float nm = 0.5f + 0.5f*sqrtf(1.f + 4.f*mom*mom);
            coef = (mom-1.f)/nm;
            mom = nm;
        }
        k_iter<<<dim3(TT/64, KDIM/128, BB), 256>>>(it, coef, first);
    }
    k_final<<<NTOT/4/256,256>>>(out);
}

// round 9
// speedup vs baseline: 2.4405x; 1.3135x over previous
#include <cuda_runtime.h>
#include <math.h>
#include <stdint.h>

#define KDIM 256
#define DDIM 128
#define BB 4
#define TT 1024
#define NG 8
#define NITER 100
#define NSQ 12
#define LAMBDA 0.01f
#define REGV 0.01f
#define NTOT (BB*KDIM*TT)

// ======================= device scratch =======================
__device__ float g_DtD[KDIM*KDIM];
__device__ float g_At[KDIM*KDIM];          // A^T, A = I - DtD/L
__device__ float g_GG[DDIM*DDIM];          // D*D^T (128x128), same nonzero spectrum
__device__ float g_M[2][DDIM*DDIM];        // squaring ping-pong
__device__ float g_scale[NSQ+1];
__device__ float g_Linv, g_lambd;
__device__ float g_DtY[NTOT];
__device__ float g_xb[2][NTOT];            // ping-pong x
__device__ float g_l1[2][NTOT];            // ping-pong l1
__device__ float g_gsum[NITER][NG];

__device__ __forceinline__ void atomicMaxPosF(float* a, float v){
    atomicMax((int*)a, __float_as_int(v));
}

// ---------------- init ----------------
__global__ void k_init(const float* __restrict__ x0){
    int i = blockIdx.x*blockDim.x + threadIdx.x;
    if (i < NTOT) g_xb[0][i] = x0[i];
    if (i < NITER*NG) ((float*)g_gsum)[i]=0.f;
    if (i <= NSQ) g_scale[i]=0.f;
}

// ---------------- DtD = D^T D (256x256) ----------------
__global__ void k_dtd(const float* __restrict__ Dict){
    int i=blockIdx.x, j=threadIdx.x;
    float a0=0.f,a1=0.f,a2=0.f,a3=0.f;
    #pragma unroll 8
    for(int d=0; d<DDIM; d+=4){
        a0 += Dict[(d  )*KDIM+i]*Dict[(d  )*KDIM+j];
        a1 += Dict[(d+1)*KDIM+i]*Dict[(d+1)*KDIM+j];
        a2 += Dict[(d+2)*KDIM+i]*Dict[(d+2)*KDIM+j];
        a3 += Dict[(d+3)*KDIM+i]*Dict[(d+3)*KDIM+j];
    }
    g_DtD[i*KDIM+j]=(a0+a1)+(a2+a3);
}

// ---------------- GG = D D^T (128x128) ----------------
__global__ void k_gg(const float* __restrict__ Dict){
    __shared__ float sh[KDIM];
    int i=blockIdx.x, j=threadIdx.x;
    sh[j]        = Dict[i*KDIM + j];
    sh[j+128]    = Dict[i*KDIM + j + 128];
    __syncthreads();
    float a0=0.f,a1=0.f,a2=0.f,a3=0.f;
    const float* rj = Dict + j*KDIM;
    #pragma unroll 8
    for(int k=0;k<KDIM;k+=4){
        a0 += sh[k  ]*rj[k  ];
        a1 += sh[k+1]*rj[k+1];
        a2 += sh[k+2]*rj[k+2];
        a3 += sh[k+3]*rj[k+3];
    }
    float acc=(a0+a1)+(a2+a3);
    g_GG[i*DDIM+j]=acc;
    float m=fabsf(acc);
    #pragma unroll
    for(int o=16;o>0;o>>=1) m=fmaxf(m,__shfl_xor_sync(0xffffffffu,m,o));
    __shared__ float sm[4];
    if((j&31)==0) sm[j>>5]=m;
    __syncthreads();
    if(j==0){
        float mm=fmaxf(fmaxf(sm[0],sm[1]),fmaxf(sm[2],sm[3]));
        atomicMaxPosF(&g_scale[0], mm);
    }
}

// ------- 128x128 matrix squaring, full matrix cached in SMEM -------
__global__ void k_square(int step){
    extern __shared__ float sIn[];   // 128*128 floats = 64KB
    const float* __restrict__ in = (step==0)? g_GG : g_M[(step-1)&1];
    float* __restrict__ out = g_M[step&1];
    int i=blockIdx.x, j=threadIdx.x;
    #pragma unroll
    for(int r=0;r<32;r++){
        int f = j + r*128;
        ((float4*)sIn)[f] = ((const float4*)in)[f];
    }
    __syncthreads();
    float inv = 1.0f/g_scale[step];
    const float* ri = sIn + i*DDIM;
    float a0=0.f,a1=0.f,a2=0.f,a3=0.f;
    #pragma unroll 8
    for(int p=0;p<DDIM;p+=4){
        a0 += ri[p  ]*sIn[(p  )*DDIM+j];
        a1 += ri[p+1]*sIn[(p+1)*DDIM+j];
        a2 += ri[p+2]*sIn[(p+2)*DDIM+j];
        a3 += ri[p+3]*sIn[(p+3)*DDIM+j];
    }
    float acc=((a0+a1)+(a2+a3))*inv*inv;
    out[i*DDIM+j]=acc;
    float m=fabsf(acc);
    #pragma unroll
    for(int o=16;o>0;o>>=1) m=fmaxf(m,__shfl_xor_sync(0xffffffffu,m,o));
    __shared__ float sm[4];
    if((j&31)==0) sm[j>>5]=m;
    __syncthreads();
    if(j==0){
        float mm=fmaxf(fmaxf(sm[0],sm[1]),fmaxf(sm[2],sm[3]));
        atomicMaxPosF(&g_scale[step+1], mm);
    }
}

// ---------------- Rayleigh quotient on GG ----------------
__global__ void k_rayleigh(int bufidx){
    const float* __restrict__ Mf = g_M[bufidx];
    __shared__ float v[DDIM];
    __shared__ float red[DDIM];
    __shared__ int rid[DDIM];
    int j=threadIdx.x;
    red[j]=Mf[j*DDIM+j]; rid[j]=j;
    __syncthreads();
    for(int s=DDIM/2;s>0;s>>=1){
        if(j<s && red[j+s]>red[j]){ red[j]=red[j+s]; rid[j]=rid[j+s]; }
        __syncthreads();
    }
    int jstar=rid[0];
    __syncthreads();
    v[j]=Mf[j*DDIM+jstar];
    __syncthreads();
    float u=0.f;
    #pragma unroll 8
    for(int p=0;p<DDIM;p++) u += g_GG[j*DDIM+p]*v[p];
    float num=u*v[j], den=v[j]*v[j];
    red[j]=num; __syncthreads();
    for(int s=DDIM/2;s>0;s>>=1){ if(j<s) red[j]+=red[j+s]; __syncthreads(); }
    float NUM=red[0]; __syncthreads();
    red[j]=den; __syncthreads();
    for(int s=DDIM/2;s>0;s>>=1){ if(j<s) red[j]+=red[j+s]; __syncthreads(); }
    if(j==0){
        float L = NUM/red[0];
        g_Linv = 1.0f/L;
        g_lambd = LAMBDA/L;
    }
}

// ---------------- A^T build ----------------
__global__ void k_buildAt(){
    int i=blockIdx.x, j=threadIdx.x;
    float a = ((i==j)?1.f:0.f) - g_DtD[i*KDIM+j]*g_Linv;
    g_At[j*KDIM+i]=a;
}

// ---------------- DtY (fp32 SIMT, one-time) ----------------
__global__ void k_dty(const float* __restrict__ Dict, const float* __restrict__ inp){
    __shared__ float As[16][64];
    __shared__ float Bs[16][64];
    int tbase=blockIdx.x<<6, kbase=blockIdx.y<<6, b=blockIdx.z;
    int tid=threadIdx.x, tx=tid&15, ty=tid>>4;
    float acc[4][4];
    #pragma unroll
    for(int i=0;i<4;i++){
        #pragma unroll
        for(int q=0;q<4;q++) acc[i][q]=0.f;
    }
    for(int d0=0; d0<DDIM; d0+=16){
        #pragma unroll
        for(int r=0;r<4;r++){
            int e=tid + (r<<8);
            int dd=e>>6, cc=e&63;
            As[dd][cc]=Dict[(d0+dd)*KDIM + kbase+cc];
            Bs[dd][cc]=inp[(b*DDIM + d0+dd)*TT + tbase+cc];
        }
        __syncthreads();
        #pragma unroll
        for(int p=0;p<16;p++){
            float4 a=*(const float4*)&As[p][ty<<2];
            float4 bv=*(const float4*)&Bs[p][tx<<2];
            acc[0][0]+=a.x*bv.x; acc[0][1]+=a.x*bv.y; acc[0][2]+=a.x*bv.z; acc[0][3]+=a.x*bv.w;
            acc[1][0]+=a.y*bv.x; acc[1][1]+=a.y*bv.y; acc[1][2]+=a.y*bv.z; acc[1][3]+=a.y*bv.w;
            acc[2][0]+=a.z*bv.x; acc[2][1]+=a.z*bv.y; acc[2][2]+=a.z*bv.z; acc[2][3]+=a.z*bv.w;
            acc[3][0]+=a.w*bv.x; acc[3][1]+=a.w*bv.y; acc[3][2]+=a.w*bv.z; acc[3][3]+=a.w*bv.w;
        }
        __syncthreads();
    }
    #pragma unroll
    for(int i=0;i<4;i++){
        int kg=kbase+(ty<<2)+i;
        float4 o=make_float4(acc[i][0],acc[i][1],acc[i][2],acc[i][3]);
        *(float4*)&g_DtY[(b*KDIM+kg)*TT + tbase + (tx<<2)] = o;
    }
}

// ====== fused iteration v3: 128x64 tile, software-pipelined double-buffered staging ======
// Grid (TT/64=16, KDIM/128=2, BB=4) = 128 CTAs, 256 threads, 1 sync/chunk.
__global__ void __launch_bounds__(256,1) k_iter(int it, float coef, int first){
    __shared__ float As[2][16][128];
    __shared__ float Bs[2][16][64];
    __shared__ float sc[NG];
    int tid=threadIdx.x, tx=tid&15, ty=tid>>4, w=tid>>5, lane=tid&31;
    int tbase=blockIdx.x<<6, kbase=blockIdx.y<<7, b=blockIdx.z;

    const float* __restrict__ l1r = g_l1[(it+1)&1];
    float* __restrict__ l1w       = g_l1[it&1];
    const float* __restrict__ xr  = first ? g_xb[0] : g_xb[(it+1)&1];
    float* __restrict__ xw        = g_xb[it&1];
    int writer = (blockIdx.y==0);

    if (tid < NG){
        float s = g_gsum[it>0 ? it-1 : 0][tid];
        sc[tid] = (s>0.f)? fmaxf(0.f, 1.f - REGV/sqrtf(s)) : 0.f;
    }

    float acc[8][4];
    #pragma unroll
    for(int i=0;i<8;i++){
        #pragma unroll
        for(int q=0;q<4;q++) acc[i][q]=0.f;
    }

    float4 ra0, ra1, rl1, rxo;
    // ---- load chunk 0 into regs ----
    {
        int jg = ty;
        const float4* srcA=(const float4*)&g_At[jg*KDIM + kbase + tx*8];
        ra0 = srcA[0]; ra1 = srcA[1];
        size_t idx = ((size_t)(b*KDIM + jg))*TT + tbase + tx*4;
        rxo = *(const float4*)&xr[idx];
        if (!first) rl1 = *(const float4*)&l1r[idx];
    }
    __syncthreads();   // sc visible
    // ---- store chunk 0 to buf0 ----
    {
        float4 v;
        if (first){ v = rxo; }
        else {
            float scale = sc[ty>>5];   // ty<16 -> group 0 of this half... jg=ty: group (ty)>>5 == 0
            // NOTE: jg = ty in [0,16) -> jg>>5 == 0 always for chunk 0
            scale = sc[0];
            float nx0=rl1.x*scale, nx1=rl1.y*scale, nx2=rl1.z*scale, nx3=rl1.w*scale;
            v.x = nx0 + (nx0-rxo.x)*coef;
            v.y = nx1 + (nx1-rxo.y)*coef;
            v.z = nx2 + (nx2-rxo.z)*coef;
            v.w = nx3 + (nx3-rxo.w)*coef;
            if (writer){
                size_t idx = ((size_t)(b*KDIM + ty))*TT + tbase + tx*4;
                *(float4*)&xw[idx] = make_float4(nx0,nx1,nx2,nx3);
            }
        }
        *(float4*)&Bs[0][ty][tx*4] = v;
        *(float4*)&As[0][ty][tx*8]   = ra0;
        *(float4*)&As[0][ty][tx*8+4] = ra1;
    }
    // ---- load chunk 1 into regs ----
    {
        int jg = 16 + ty;
        const float4* srcA=(const float4*)&g_At[jg*KDIM + kbase + tx*8];
        ra0 = srcA[0]; ra1 = srcA[1];
        size_t idx = ((size_t)(b*KDIM + jg))*TT + tbase + tx*4;
        rxo = *(const float4*)&xr[idx];
        if (!first) rl1 = *(const float4*)&l1r[idx];
    }
    __syncthreads();   // buf0 visible

    for(int c=0;c<16;c++){
        if (c < 15){
            // store chunk c+1 (in regs) into buf[(c+1)&1]
            int cc = c+1;
            int jg = cc*16 + ty;
            float4 v;
            if (first){ v = rxo; }
            else {
                float scale = sc[jg>>5];
                float nx0=rl1.x*scale, nx1=rl1.y*scale, nx2=rl1.z*scale, nx3=rl1.w*scale;
                v.x = nx0 + (nx0-rxo.x)*coef;
                v.y = nx1 + (nx1-rxo.y)*coef;
                v.z = nx2 + (nx2-rxo.z)*coef;
                v.w = nx3 + (nx3-rxo.w)*coef;
                if (writer){
                    size_t idx = ((size_t)(b*KDIM + jg))*TT + tbase + tx*4;
                    *(float4*)&xw[idx] = make_float4(nx0,nx1,nx2,nx3);
                }
            }
            int bsel = cc&1;
            *(float4*)&Bs[bsel][ty][tx*4] = v;
            *(float4*)&As[bsel][ty][tx*8]   = ra0;
            *(float4*)&As[bsel][ty][tx*8+4] = ra1;
        }
        if (c < 14){
            // issue global loads for chunk c+2 (latency hidden behind FMA below)
            int jg = (c+2)*16 + ty;
            const float4* srcA=(const float4*)&g_At[jg*KDIM + kbase + tx*8];
            ra0 = srcA[0]; ra1 = srcA[1];
            size_t idx = ((size_t)(b*KDIM + jg))*TT + tbase + tx*4;
            rxo = *(const float4*)&xr[idx];
            if (!first) rl1 = *(const float4*)&l1r[idx];
        }
        // ---- FMA over buf[c&1] ----
        {
            int bsel = c&1;
            #pragma unroll
            for(int p=0;p<16;p++){
                float4 a0=*(const float4*)&As[bsel][p][ty*8];
                float4 a1=*(const float4*)&As[bsel][p][ty*8+4];
                float4 bv=*(const float4*)&Bs[bsel][p][tx*4];
                acc[0][0]+=a0.x*bv.x; acc[0][1]+=a0.x*bv.y; acc[0][2]+=a0.x*bv.z; acc[0][3]+=a0.x*bv.w;
                acc[1][0]+=a0.y*bv.x; acc[1][1]+=a0.y*bv.y; acc[1][2]+=a0.y*bv.z; acc[1][3]+=a0.y*bv.w;
                acc[2][0]+=a0.z*bv.x; acc[2][1]+=a0.z*bv.y; acc[2][2]+=a0.z*bv.z; acc[2][3]+=a0.z*bv.w;
                acc[3][0]+=a0.w*bv.x; acc[3][1]+=a0.w*bv.y; acc[3][2]+=a0.w*bv.z; acc[3][3]+=a0.w*bv.w;
                acc[4][0]+=a1.x*bv.x; acc[4][1]+=a1.x*bv.y; acc[4][2]+=a1.x*bv.z; acc[4][3]+=a1.x*bv.w;
                acc[5][0]+=a1.y*bv.x; acc[5][1]+=a1.y*bv.y; acc[5][2]+=a1.y*bv.z; acc[5][3]+=a1.y*bv.w;
                acc[6][0]+=a1.z*bv.x; acc[6][1]+=a1.z*bv.y; acc[6][2]+=a1.z*bv.z; acc[6][3]+=a1.z*bv.w;
                acc[7][0]+=a1.w*bv.x; acc[7][1]+=a1.w*bv.y; acc[7][2]+=a1.w*bv.z; acc[7][3]+=a1.w*bv.w;
            }
        }
        if (c < 15) __syncthreads();
    }

    // ---- epilogue: + DtY*Linv, soft-threshold, write l1, group ssq ----
    float Linv=g_Linv, lam=g_lambd;
    float ssq=0.f;
    #pragma unroll
    for(int i=0;i<8;i++){
        int row = kbase + ty*8 + i;
        size_t base=((size_t)(b*KDIM+row))*TT + tbase + tx*4;
        float4 dty=*(const float4*)&g_DtY[base];
        float s0=acc[i][0]+dty.x*Linv;
        float s1=acc[i][1]+dty.y*Linv;
        float s2=acc[i][2]+dty.z*Linv;
        float s3=acc[i][3]+dty.w*Linv;
        float v0=fmaxf(s0-lam,0.f)+fminf(s0+lam,0.f);
        float v1=fmaxf(s1-lam,0.f)+fminf(s1+lam,0.f);
        float v2=fmaxf(s2-lam,0.f)+fminf(s2+lam,0.f);
        float v3=fmaxf(s3-lam,0.f)+fminf(s3+lam,0.f);
        *(float4*)&l1w[base]=make_float4(v0,v1,v2,v3);
        ssq += v0*v0+v1*v1+v2*v2+v3*v3;
    }
    // warp w covers rows kbase+16w..+15 -> group blockIdx.y*4 + (w>>1)
    #pragma unroll
    for(int o=16;o>0;o>>=1) ssq += __shfl_xor_sync(0xffffffffu, ssq, o);
    if (lane==0) atomicAdd(&g_gsum[it][blockIdx.y*4 + (w>>1)], ssq);
}

// ---------------- final: x_100 = l1_99 * group_scale(gsum_99) ----------------
__global__ void k_final(float* __restrict__ dout){
    int i = blockIdx.x*blockDim.x + threadIdx.x;
    int idx = i<<2;
    int k = (idx>>10) & (KDIM-1);
    float s = g_gsum[NITER-1][k>>5];
    float scale = (s>0.f)? fmaxf(0.f, 1.f - REGV/sqrtf(s)) : 0.f;
    float4 l1 = *(const float4*)&g_l1[(NITER-1)&1][idx];
    *(float4*)&dout[idx] = make_float4(l1.x*scale, l1.y*scale, l1.z*scale, l1.w*scale);
}

// ======================= host launcher =======================
extern "C" void kernel_launch(void* const* d_in, const int* in_sizes, int n_in,
                              void* d_out, int out_size) {
    const float *Dict=nullptr, *inp=nullptr, *x0=nullptr;
    for(int i=0;i<n_in;i++){
        if      (in_sizes[i]==KDIM*DDIM)  Dict=(const float*)d_in[i];
        else if (in_sizes[i]==BB*DDIM*TT) inp =(const float*)d_in[i];
        else if (in_sizes[i]==NTOT)       x0  =(const float*)d_in[i];
    }
    float* out=(float*)d_out;

    static int attr_set = 0;
    if (!attr_set){
        cudaFuncSetAttribute(k_square, cudaFuncAttributeMaxDynamicSharedMemorySize,
                             DDIM*DDIM*sizeof(float));
        attr_set = 1;
    }

    k_init<<<(NTOT+255)/256,256>>>(x0);
    k_dtd<<<KDIM,KDIM>>>(Dict);
    k_gg<<<DDIM,DDIM>>>(Dict);
    for(int s=0;s<NSQ;s++) k_square<<<DDIM,DDIM,DDIM*DDIM*sizeof(float)>>>(s);
    k_rayleigh<<<1,DDIM>>>((NSQ-1)&1);
    k_buildAt<<<KDIM,KDIM>>>();
    k_dty<<<dim3(TT/64, KDIM/64, BB),256>>>(Dict, inp);

    float mom=1.f;
    for(int it=0; it<NITER; it++){
        float coef=0.f;
        int first = (it==0)?1:0;
        if(!first){
            float nm = 0.5f + 0.5f*sqrtf(1.f + 4.f*mom*mom);
            coef = (mom-1.f)/nm;
            mom = nm;
        }
        k_iter<<<dim3(TT/64, KDIM/128, BB), 256>>>(it, coef, first);
    }
    k_final<<<NTOT/4/256,256>>>(out);
}

// round 10
// speedup vs baseline: 2.8640x; 1.1735x over previous
#include <cuda_runtime.h>
#include <math.h>
#include <stdint.h>

#define KDIM 256
#define DDIM 128
#define BB 4
#define TT 1024
#define NG 8
#define NITER 100
#define NSQ 12
#define LAMBDA 0.01f
#define REGV 0.01f
#define NTOT (BB*KDIM*TT)
#define NCTA 128

// ======================= device scratch =======================
__device__ float g_DtD[KDIM*KDIM];
__device__ float g_GG[DDIM*DDIM];
__device__ float g_M[2][DDIM*DDIM];
__device__ float g_scale[NSQ+1];
__device__ float g_Linv, g_lambd;
__device__ float g_xb[2][NTOT];
__device__ float g_l1[2][NTOT];
__device__ float g_gsum[NITER][NG];
__device__ unsigned g_barcnt, g_bargen;

__device__ __forceinline__ void atomicMaxPosF(float* a, float v){
    atomicMax((int*)a, __float_as_int(v));
}
// packed fp32x2 FMA (Blackwell baseline PTX)
#define FMA2(d,a,bb) asm("fma.rn.f32x2 %0, %1, %2, %0;" : "+l"(d) : "l"(a), "l"(bb))
#define SPLAT2(d,f)  asm("mov.b64 %0, {%1,%1};" : "=l"(d) : "f"(f))
#define UNPK2(lo,hi,s) asm("mov.b64 {%0,%1}, %2;" : "=f"(lo), "=f"(hi) : "l"(s))

// software grid barrier (128 co-resident CTAs; 1 CTA/SM by SMEM footprint)
__device__ __forceinline__ void gbar(){
    __syncthreads();
    if (threadIdx.x==0){
        __threadfence();
        unsigned gen = *(volatile unsigned*)&g_bargen;
        if (atomicAdd(&g_barcnt,1u)==NCTA-1u){
            g_barcnt = 0u;
            __threadfence();
            atomicAdd(&g_bargen,1u);
        } else {
            while (*(volatile unsigned*)&g_bargen == gen) __nanosleep(64);
        }
    }
    __syncthreads();
}

// ---------------- init ----------------
__global__ void k_init(){
    int i=threadIdx.x;
    for(int f=i; f<NITER*NG; f+=blockDim.x) ((float*)g_gsum)[f]=0.f;
    if(i<=NSQ) g_scale[i]=0.f;
    if(i==0){ g_barcnt=0u; g_bargen=0u; }
}

// ======================= persistent kernel =======================
#define SA_F   (KDIM*DDIM)     // 32768 floats: A^T half  [j=0..255][klocal=0..127]
#define SDTY_F (DDIM*64)       // 8192  floats: DtY tile  [klocal][tlocal]
#define SB_F   (2*16*64)       // 2048  floats: B double buffer
#define SMEM_BYTES ((SA_F+SDTY_F+SB_F+16)*4)

__global__ void __launch_bounds__(256,1) k_persist(
    const float* __restrict__ Dict, const float* __restrict__ inp,
    const float* __restrict__ x0, float* __restrict__ out)
{
    extern __shared__ float smf[];
    float* sA   = smf;
    float* sDtY = smf + SA_F;
    float* sB   = smf + SA_F + SDTY_F;
    float* sc   = smf + SA_F + SDTY_F + SB_F;

    int tid=threadIdx.x, tx=tid&15, ty=tid>>4, w=tid>>5, lane=tid&31;
    int tb=blockIdx.x<<6, kh=blockIdx.y, kbase=kh<<7, b=blockIdx.z;
    int cid = blockIdx.x + (blockIdx.y<<4) + (blockIdx.z<<5);

    // ---------- S1a: DtD rows 2cid, 2cid+1 ----------
    #pragma unroll
    for(int r=0;r<2;r++){
        int i = cid*2+r, j=tid;
        float a0=0.f,a1=0.f,a2=0.f,a3=0.f;
        #pragma unroll 8
        for(int d=0;d<DDIM;d+=4){
            a0+=Dict[(d  )*KDIM+i]*Dict[(d  )*KDIM+j];
            a1+=Dict[(d+1)*KDIM+i]*Dict[(d+1)*KDIM+j];
            a2+=Dict[(d+2)*KDIM+i]*Dict[(d+2)*KDIM+j];
            a3+=Dict[(d+3)*KDIM+i]*Dict[(d+3)*KDIM+j];
        }
        g_DtD[i*KDIM+j]=(a0+a1)+(a2+a3);
    }
    // ---------- S1b: GG row cid ----------
    if(tid<DDIM){
        int i=cid, j=tid;
        float a0=0.f,a1=0.f,a2=0.f,a3=0.f;
        #pragma unroll 8
        for(int k=0;k<KDIM;k+=4){
            a0+=Dict[i*KDIM+k  ]*Dict[j*KDIM+k  ];
            a1+=Dict[i*KDIM+k+1]*Dict[j*KDIM+k+1];
            a2+=Dict[i*KDIM+k+2]*Dict[j*KDIM+k+2];
            a3+=Dict[i*KDIM+k+3]*Dict[j*KDIM+k+3];
        }
        float acc=(a0+a1)+(a2+a3);
        g_GG[i*DDIM+j]=acc;
        float m=fabsf(acc);
        #pragma unroll
        for(int o=16;o>0;o>>=1) m=fmaxf(m,__shfl_xor_sync(0xffffffffu,m,o));
        if((tid&31)==0) atomicMaxPosF(&g_scale[0], m);
    }
    // ---------- S1c: DtY tile -> sDtY (CTA-local, persistent) ----------
    {
        float da[8][4];
        #pragma unroll
        for(int i=0;i<8;i++){
            #pragma unroll
            for(int q=0;q<4;q++) da[i][q]=0.f;
        }
        for(int d=0; d<DDIM; d++){
            float4 a0=*(const float4*)&Dict[d*KDIM + kbase + ty*8];
            float4 a1=*(const float4*)&Dict[d*KDIM + kbase + ty*8 + 4];
            float4 bv=*(const float4*)&inp[((size_t)b*DDIM + d)*TT + tb + tx*4];
            da[0][0]+=a0.x*bv.x; da[0][1]+=a0.x*bv.y; da[0][2]+=a0.x*bv.z; da[0][3]+=a0.x*bv.w;
            da[1][0]+=a0.y*bv.x; da[1][1]+=a0.y*bv.y; da[1][2]+=a0.y*bv.z; da[1][3]+=a0.y*bv.w;
            da[2][0]+=a0.z*bv.x; da[2][1]+=a0.z*bv.y; da[2][2]+=a0.z*bv.z; da[2][3]+=a0.z*bv.w;
            da[3][0]+=a0.w*bv.x; da[3][1]+=a0.w*bv.y; da[3][2]+=a0.w*bv.z; da[3][3]+=a0.w*bv.w;
            da[4][0]+=a1.x*bv.x; da[4][1]+=a1.x*bv.y; da[4][2]+=a1.x*bv.z; da[4][3]+=a1.x*bv.w;
            da[5][0]+=a1.y*bv.x; da[5][1]+=a1.y*bv.y; da[5][2]+=a1.y*bv.z; da[5][3]+=a1.y*bv.w;
            da[6][0]+=a1.z*bv.x; da[6][1]+=a1.z*bv.y; da[6][2]+=a1.z*bv.z; da[6][3]+=a1.z*bv.w;
            da[7][0]+=a1.w*bv.x; da[7][1]+=a1.w*bv.y; da[7][2]+=a1.w*bv.z; da[7][3]+=a1.w*bv.w;
        }
        #pragma unroll
        for(int i=0;i<8;i++)
            *(float4*)&sDtY[(ty*8+i)*64 + tx*4] = make_float4(da[i][0],da[i][1],da[i][2],da[i][3]);
    }
    gbar();

    // ---------- S2: 12 normalized squarings of GG ----------
    for(int s=0;s<NSQ;s++){
        const float* __restrict__ in = (s==0)? g_GG : g_M[(s-1)&1];
        float* __restrict__ outm = g_M[s&1];
        if(tid<DDIM){
            float inv = 1.0f/__ldcg(&g_scale[s]);
            int i=cid, j=tid;
            float a0=0.f,a1=0.f,a2=0.f,a3=0.f;
            #pragma unroll 8
            for(int p=0;p<DDIM;p+=4){
                a0+=__ldcg(&in[i*DDIM+p  ])*__ldcg(&in[(p  )*DDIM+j]);
                a1+=__ldcg(&in[i*DDIM+p+1])*__ldcg(&in[(p+1)*DDIM+j]);
                a2+=__ldcg(&in[i*DDIM+p+2])*__ldcg(&in[(p+2)*DDIM+j]);
                a3+=__ldcg(&in[i*DDIM+p+3])*__ldcg(&in[(p+3)*DDIM+j]);
            }
            float acc=((a0+a1)+(a2+a3))*inv*inv;
            outm[i*DDIM+j]=acc;
            float m=fabsf(acc);
            #pragma unroll
            for(int o=16;o>0;o>>=1) m=fmaxf(m,__shfl_xor_sync(0xffffffffu,m,o));
            if((tid&31)==0) atomicMaxPosF(&g_scale[s+1], m);
        }
        gbar();
    }

    // ---------- S3: Rayleigh quotient (CTA 0) ----------
    if(cid==0){
        float* v=sB; float* red=sB+128; int* rid=(int*)(sB+256);
        const float* __restrict__ Mf = g_M[(NSQ-1)&1];
        int j=tid;
        if(j<DDIM){ red[j]=__ldcg(&Mf[j*DDIM+j]); rid[j]=j; }
        __syncthreads();
        for(int s2=DDIM/2;s2>0;s2>>=1){
            if(j<s2 && red[j+s2]>red[j]){ red[j]=red[j+s2]; rid[j]=rid[j+s2]; }
            __syncthreads();
        }
        int jstar=rid[0];
        __syncthreads();
        if(j<DDIM) v[j]=__ldcg(&Mf[j*DDIM+jstar]);
        __syncthreads();
        float u=0.f;
        if(j<DDIM){
            #pragma unroll 8
            for(int p=0;p<DDIM;p++) u += __ldcg(&g_GG[j*DDIM+p])*v[p];
            red[j]=u*v[j];
        }
        __syncthreads();
        for(int s2=DDIM/2;s2>0;s2>>=1){ if(j<s2) red[j]+=red[j+s2]; __syncthreads(); }
        float NUM=red[0];
        __syncthreads();
        if(j<DDIM) red[j]=v[j]*v[j];
        __syncthreads();
        for(int s2=DDIM/2;s2>0;s2>>=1){ if(j<s2) red[j]+=red[j+s2]; __syncthreads(); }
        if(j==0){
            float L = NUM/red[0];
            g_Linv = 1.0f/L;
            g_lambd = LAMBDA/L;
        }
    }
    gbar();

    // ---------- S4: build persistent A^T half in SMEM ----------
    float Linv=__ldcg(&g_Linv), lam=__ldcg(&g_lambd);
    for(int f=tid; f<SA_F; f+=256){
        int j=f>>7, kl=f&127;
        int col = kbase+kl;
        sA[f] = ((j==col)?1.f:0.f) - __ldcg(&g_DtD[j*KDIM+col])*Linv;
    }
    __syncthreads();

    // ---------- iterations ----------
    float mom=1.f, coef=0.f;
    float vv[8][4];
    int writer = (kh==0);

    for(int it=0; it<NITER; it++){
        int first = (it==0);
        const float* __restrict__ l1r = g_l1[(it+1)&1];
        float* __restrict__ l1w       = g_l1[it&1];
        const float* __restrict__ xr  = first ? x0 : g_xb[(it+1)&1];
        float* __restrict__ xw        = g_xb[it&1];

        if(tid<NG){
            float s = first ? 1.f : __ldcg(&g_gsum[it-1][tid]);
            sc[tid] = (s>0.f)? fmaxf(0.f, 1.f - REGV/sqrtf(s)) : 0.f;
        }
        if(!first){
            float nm = 0.5f + 0.5f*sqrtf(1.f + 4.f*mom*mom);
            coef = (mom-1.f)/nm; mom = nm;
        }

        uint64_t acc2[4][4];
        #pragma unroll
        for(int pp=0;pp<4;pp++){
            #pragma unroll
            for(int q=0;q<4;q++) acc2[pp][q]=0ull;
        }

        float4 rl1, rxo;
        // load chunk 0
        {
            size_t idx=((size_t)(b*KDIM+ty))*TT + tb + tx*4;
            rxo = __ldcg((const float4*)&xr[idx]);
            if(!first) rl1 = __ldcg((const float4*)&l1r[idx]);
        }
        __syncthreads();   // sc visible
        // store chunk 0 -> buf0
        {
            float4 v;
            if(first){ v=rxo; }
            else{
                float scale = sc[0];  // jg<16 -> group 0
                float nx0=rl1.x*scale, nx1=rl1.y*scale, nx2=rl1.z*scale, nx3=rl1.w*scale;
                v.x=nx0+(nx0-rxo.x)*coef; v.y=nx1+(nx1-rxo.y)*coef;
                v.z=nx2+(nx2-rxo.z)*coef; v.w=nx3+(nx3-rxo.w)*coef;
                if(writer){
                    size_t idx=((size_t)(b*KDIM+ty))*TT + tb + tx*4;
                    *(float4*)&xw[idx]=make_float4(nx0,nx1,nx2,nx3);
                }
            }
            *(float4*)&sB[(0*16+ty)*64 + tx*4] = v;
        }
        // load chunk 1
        {
            size_t idx=((size_t)(b*KDIM+16+ty))*TT + tb + tx*4;
            rxo = __ldcg((const float4*)&xr[idx]);
            if(!first) rl1 = __ldcg((const float4*)&l1r[idx]);
        }
        __syncthreads();   // buf0 visible

        for(int c=0;c<16;c++){
            if(c<15){
                int cc=c+1, jg=cc*16+ty, bsel=cc&1;
                float4 v;
                if(first){ v=rxo; }
                else{
                    float scale = sc[jg>>5];
                    float nx0=rl1.x*scale, nx1=rl1.y*scale, nx2=rl1.z*scale, nx3=rl1.w*scale;
                    v.x=nx0+(nx0-rxo.x)*coef; v.y=nx1+(nx1-rxo.y)*coef;
                    v.z=nx2+(nx2-rxo.z)*coef; v.w=nx3+(nx3-rxo.w)*coef;
                    if(writer){
                        size_t idx=((size_t)(b*KDIM+jg))*TT + tb + tx*4;
                        *(float4*)&xw[idx]=make_float4(nx0,nx1,nx2,nx3);
                    }
                }
                *(float4*)&sB[(bsel*16+ty)*64 + tx*4] = v;
            }
            if(c<14){
                int jg=(c+2)*16+ty;
                size_t idx=((size_t)(b*KDIM+jg))*TT + tb + tx*4;
                rxo = __ldcg((const float4*)&xr[idx]);
                if(!first) rl1 = __ldcg((const float4*)&l1r[idx]);
            }
            // ---- f32x2 FMA over chunk c ----
            {
                int base=(c&1)*1024;
                #pragma unroll
                for(int p=0;p<16;p++){
                    const float* ar=&sA[(c*16+p)*128 + ty*8];
                    ulonglong2 A01=*(const ulonglong2*)ar;
                    ulonglong2 A23=*(const ulonglong2*)(ar+4);
                    float4 bv=*(const float4*)&sB[base + p*64 + tx*4];
                    uint64_t s0,s1,s2,s3;
                    SPLAT2(s0,bv.x); SPLAT2(s1,bv.y); SPLAT2(s2,bv.z); SPLAT2(s3,bv.w);
                    FMA2(acc2[0][0],A01.x,s0); FMA2(acc2[0][1],A01.x,s1); FMA2(acc2[0][2],A01.x,s2); FMA2(acc2[0][3],A01.x,s3);
                    FMA2(acc2[1][0],A01.y,s0); FMA2(acc2[1][1],A01.y,s1); FMA2(acc2[1][2],A01.y,s2); FMA2(acc2[1][3],A01.y,s3);
                    FMA2(acc2[2][0],A23.x,s0); FMA2(acc2[2][1],A23.x,s1); FMA2(acc2[2][2],A23.x,s2); FMA2(acc2[2][3],A23.x,s3);
                    FMA2(acc2[3][0],A23.y,s0); FMA2(acc2[3][1],A23.y,s1); FMA2(acc2[3][2],A23.y,s2); FMA2(acc2[3][3],A23.y,s3);
                }
            }
            if(c<15) __syncthreads();
        }

        // ---- epilogue: unpack, + DtY*Linv, prox, write l1, group ssq ----
        #pragma unroll
        for(int pp=0;pp<4;pp++){
            #pragma unroll
            for(int q=0;q<4;q++){
                float lo,hi; UNPK2(lo,hi,acc2[pp][q]);
                vv[2*pp][q]=lo; vv[2*pp+1][q]=hi;
            }
        }
        float ssq=0.f;
        #pragma unroll
        for(int i=0;i<8;i++){
            int rl=ty*8+i;
            float4 dty=*(const float4*)&sDtY[rl*64 + tx*4];
            float s0=vv[i][0]+dty.x*Linv;
            float s1=vv[i][1]+dty.y*Linv;
            float s2=vv[i][2]+dty.z*Linv;
            float s3=vv[i][3]+dty.w*Linv;
            float v0=fmaxf(s0-lam,0.f)+fminf(s0+lam,0.f);
            float v1=fmaxf(s1-lam,0.f)+fminf(s1+lam,0.f);
            float v2=fmaxf(s2-lam,0.f)+fminf(s2+lam,0.f);
            float v3=fmaxf(s3-lam,0.f)+fminf(s3+lam,0.f);
            vv[i][0]=v0; vv[i][1]=v1; vv[i][2]=v2; vv[i][3]=v3;
            *(float4*)&l1w[((size_t)(b*KDIM+kbase+rl))*TT + tb + tx*4] = make_float4(v0,v1,v2,v3);
            ssq += v0*v0+v1*v1+v2*v2+v3*v3;
        }
        #pragma unroll
        for(int o=16;o>0;o>>=1) ssq += __shfl_xor_sync(0xffffffffu, ssq, o);
        if(lane==0) atomicAdd(&g_gsum[it][kh*4 + (w>>1)], ssq);
        gbar();
    }

    // ---------- final: out = l1_99 * group_scale(gsum_99) ----------
    if(tid<NG){
        float s = __ldcg(&g_gsum[NITER-1][tid]);
        sc[tid] = (s>0.f)? fmaxf(0.f, 1.f - REGV/sqrtf(s)) : 0.f;
    }
    __syncthreads();
    #pragma unroll
    for(int i=0;i<8;i++){
        int rl=ty*8+i, row=kbase+rl;
        float scale = sc[row>>5];
        *(float4*)&out[((size_t)(b*KDIM+row))*TT + tb + tx*4] =
            make_float4(vv[i][0]*scale, vv[i][1]*scale, vv[i][2]*scale, vv[i][3]*scale);
    }
}

// ======================= host launcher =======================
extern "C" void kernel_launch(void* const* d_in, const int* in_sizes, int n_in,
                              void* d_out, int out_size) {
    const float *Dict=nullptr, *inp=nullptr, *x0=nullptr;
    for(int i=0;i<n_in;i++){
        if      (in_sizes[i]==KDIM*DDIM)  Dict=(const float*)d_in[i];
        else if (in_sizes[i]==BB*DDIM*TT) inp =(const float*)d_in[i];
        else if (in_sizes[i]==NTOT)       x0  =(const float*)d_in[i];
    }
    float* out=(float*)d_out;

    static int attr_set = 0;
    if (!attr_set){
        cudaFuncSetAttribute(k_persist, cudaFuncAttributeMaxDynamicSharedMemorySize, SMEM_BYTES);
        attr_set = 1;
    }

    k_init<<<1,1024>>>();
    k_persist<<<dim3(16,2,4), 256, SMEM_BYTES>>>(Dict, inp, x0, out);
}